// round 3
// baseline (speedup 1.0000x reference)
#include <cuda_runtime.h>
#include <math.h>

// Problem constants
#define B_  16
#define N_  577
#define D_  1024
#define E_  8
#define R_  16
#define C3_ 3072
#define TOPK 2

// Output layout (all six reference outputs concatenated, fp32)
#define WU_SIZE   (B_ * N_ * C3_)          // 28,366,848
#define RL_OFF    (WU_SIZE)                // router_logits [16,8]
#define TI_OFF    (RL_OFF + B_ * E_)       // top_idx as float [16,2]
#define EW_OFF    (TI_OFF + B_ * TOPK)     // expert_weights [16,8]
#define IMP_OFF   (EW_OFF + B_ * E_)       // importance [8]
#define LOAD_OFF  (IMP_OFF + E_)           // load [8]
#define OUT_TOTAL (LOAD_OFF + E_)          // 28,367,152

// Scratch (no allocations allowed -> device globals)
__device__ float g_pooled[B_ * D_];   // token sums over N
__device__ float g_logits[B_ * E_];
__device__ int   g_sel[B_ * TOPK];
__device__ float g_coef[B_ * TOPK];   // softmax weight * scaling, folded into U

// ---------------------------------------------------------------------------
// Kernel 0: zero pooled scratch (must rerun every graph replay)
// ---------------------------------------------------------------------------
__global__ void zero_pooled_kernel() {
    g_pooled[blockIdx.x * 1024 + threadIdx.x] = 0.0f;
}

// ---------------------------------------------------------------------------
// Kernel 1: pooled[b][d] = sum_n tokens[b][n][d]  (partial sums + atomics)
// grid (8 chunks, 16 batches), 256 threads; thread owns 4 consecutive d (float4)
// ---------------------------------------------------------------------------
__global__ void pool_kernel(const float* __restrict__ tokens) {
    int b = blockIdx.y;
    int chunk = blockIdx.x;
    int t = threadIdx.x;
    int n0 = chunk * 73;
    int n1 = min(N_, n0 + 73);

    float4 acc = make_float4(0.f, 0.f, 0.f, 0.f);
    const float* base = tokens + ((size_t)b * N_) * D_;
    for (int n = n0; n < n1; n++) {
        float4 v = *(const float4*)&base[n * D_ + t * 4];
        acc.x += v.x; acc.y += v.y; acc.z += v.z; acc.w += v.w;
    }
    float* p = &g_pooled[b * D_ + t * 4];
    atomicAdd(p + 0, acc.x);
    atomicAdd(p + 1, acc.y);
    atomicAdd(p + 2, acc.z);
    atomicAdd(p + 3, acc.w);
}

// ---------------------------------------------------------------------------
// Kernel 2: router logits. One warp per (b, e). 4 blocks x 1024 threads.
// logits[b][e] = (1/N) * sum_d pooled_sum[b][d] * gate_w[d][e]
// ---------------------------------------------------------------------------
__global__ void router_kernel(const float* __restrict__ gate_w,
                              float* __restrict__ out, int write_aux) {
    int w = blockIdx.x * (blockDim.x / 32) + threadIdx.x / 32;
    int lane = threadIdx.x & 31;
    if (w >= B_ * E_) return;
    int b = w / E_;
    int e = w % E_;

    float acc = 0.f;
    for (int d = lane; d < D_; d += 32)
        acc += g_pooled[b * D_ + d] * gate_w[d * E_ + e];
    #pragma unroll
    for (int off = 16; off > 0; off >>= 1)
        acc += __shfl_down_sync(0xffffffffu, acc, off);
    if (lane == 0) {
        float lg = acc * (1.0f / (float)N_);
        g_logits[b * E_ + e] = lg;
        if (write_aux) out[RL_OFF + b * E_ + e] = lg;
    }
}

// ---------------------------------------------------------------------------
// Kernel 3: top-2 + softmax + small outputs + per-batch selection scratch
// single block, 128 threads
// ---------------------------------------------------------------------------
__global__ void topk_kernel(const float* __restrict__ scaling,
                            float* __restrict__ out, int write_aux) {
    __shared__ float ew[B_][E_];
    __shared__ int   sel_s[B_][TOPK];
    int t = threadIdx.x;

    if (t < B_ * E_) ew[t / E_][t % E_] = 0.0f;
    __syncthreads();

    if (t < B_) {
        int b = t;
        float v[E_];
        #pragma unroll
        for (int e = 0; e < E_; e++) v[e] = g_logits[b * E_ + e];
        int m1 = 0;
        #pragma unroll
        for (int e = 1; e < E_; e++) if (v[e] > v[m1]) m1 = e;
        int m2 = (m1 == 0) ? 1 : 0;
        #pragma unroll
        for (int e = 0; e < E_; e++)
            if (e != m1 && v[e] > v[m2]) m2 = e;

        float e2 = expf(v[m2] - v[m1]);
        float inv = 1.0f / (1.0f + e2);
        float w1 = inv;
        float w2 = e2 * inv;

        ew[b][m1] = w1;
        ew[b][m2] = w2;
        sel_s[b][0] = m1;
        sel_s[b][1] = m2;
        g_sel[b * 2 + 0] = m1;
        g_sel[b * 2 + 1] = m2;
        g_coef[b * 2 + 0] = w1 * scaling[m1];
        g_coef[b * 2 + 1] = w2 * scaling[m2];
        if (write_aux) {
            out[TI_OFF + b * 2 + 0] = (float)m1;
            out[TI_OFF + b * 2 + 1] = (float)m2;
        }
    }
    __syncthreads();

    if (write_aux) {
        if (t < B_ * E_) out[EW_OFF + t] = ew[t / E_][t % E_];
        if (t < E_) {
            float imp = 0.f;
            int ld = 0;
            for (int b = 0; b < B_; b++) {
                imp += ew[b][t];
                ld += (sel_s[b][0] == t) + (sel_s[b][1] == t);
            }
            out[IMP_OFF + t] = imp;
            out[LOAD_OFF + t] = (float)ld;
        }
    }
}

// ---------------------------------------------------------------------------
// Kernel 4: fused per-(batch, 32-token tile):
//   Phase 1: U[32n x 32j] = T[32 x 1024] @ Asel^T ; fold coef into U
//   Phase 2: out[32n x 3072c] = U @ Bsel^T, streamed in 128-wide C chunks
// ---------------------------------------------------------------------------
#define NT 32     // token rows per block
#define KC 64     // k-chunk in phase 1
#define CC 128    // c-chunk in phase 2

__global__ __launch_bounds__(256)
void moe_lora_kernel(const float* __restrict__ tokens,
                     const float* __restrict__ lora_a,
                     const float* __restrict__ lora_b,
                     float* __restrict__ out) {
    __shared__ union {
        struct { float T[NT][KC + 4]; float A[NT][KC + 4]; } p1;  // 17,408 B
        float Bm[CC][36];                                         // 18,432 B
    } sm;
    __shared__ float Usm[NT][36];

    const int b  = blockIdx.y;
    const int n0 = blockIdx.x * NT;
    const int tid = threadIdx.x;
    const int ty = tid / 32;      // 0..7
    const int tx = tid & 31;      // 0..31

    const int s0 = g_sel[b * 2 + 0];
    const int s1 = g_sel[b * 2 + 1];
    const float c0f = g_coef[b * 2 + 0];
    const float c1f = g_coef[b * 2 + 1];

    // ---------------- Phase 1: U tile ----------------
    // thread computes U[4*ty + i][tx], i = 0..3
    float acc[4] = {0.f, 0.f, 0.f, 0.f};
    const int tok_base = (b * N_ + n0) * D_;

    for (int k0 = 0; k0 < D_; k0 += KC) {
        // load T (32 x 64) and A (32 x 64) as float4s: 512 vec4 each, 2/thread
        #pragma unroll
        for (int i = 0; i < 2; i++) {
            int idx = tid + i * 256;
            int r = idx >> 4;          // 0..31
            int q = idx & 15;          // 0..15
            float4 tv = make_float4(0.f, 0.f, 0.f, 0.f);
            if (n0 + r < N_)
                tv = *(const float4*)&tokens[tok_base + r * D_ + k0 + q * 4];
            *(float4*)&sm.p1.T[r][q * 4] = tv;

            int e  = (r < 16) ? s0 : s1;
            const float* ar = lora_a + ((e * R_ + (r & 15)) * D_);
            *(float4*)&sm.p1.A[r][q * 4] = *(const float4*)&ar[k0 + q * 4];
        }
        __syncthreads();

        #pragma unroll
        for (int kk = 0; kk < KC; kk += 4) {
            float4 av = *(const float4*)&sm.p1.A[tx][kk];
            #pragma unroll
            for (int i = 0; i < 4; i++) {
                float4 tv = *(const float4*)&sm.p1.T[ty * 4 + i][kk];
                acc[i] += tv.x * av.x + tv.y * av.y + tv.z * av.z + tv.w * av.w;
            }
        }
        __syncthreads();
    }

    // fold gating coefficient (w * scaling) into U
    {
        float cf = (tx < 16) ? c0f : c1f;
        #pragma unroll
        for (int i = 0; i < 4; i++)
            Usm[ty * 4 + i][tx] = acc[i] * cf;
    }
    __syncthreads();

    // ---------------- Phase 2: output tile ----------------
    // thread computes out rows n = ty + 8*i (i<4), cols c = c0 + tx + 32*l (l<4)
    const int out_base = (b * N_ + n0) * C3_;

    for (int c0 = 0; c0 < C3_; c0 += CC) {
        // load combined B chunk: row c holds [lora_b[s0][c][:16], lora_b[s1][c][:16]]
        #pragma unroll
        for (int i = 0; i < 4; i++) {
            int idx = tid + i * 256;
            int c = idx >> 3;          // 0..127
            int q = idx & 7;           // 0..7 (vec4 within 32-wide row)
            int e = (q < 4) ? s0 : s1;
            const float4* src =
                (const float4*)&lora_b[(e * C3_ + c0 + c) * R_ + (q & 3) * 4];
            *(float4*)&sm.Bm[c][q * 4] = *src;
        }
        __syncthreads();

        float o[4][4];
        #pragma unroll
        for (int i = 0; i < 4; i++)
            #pragma unroll
            for (int l = 0; l < 4; l++) o[i][l] = 0.f;

        #pragma unroll
        for (int j4 = 0; j4 < 32; j4 += 4) {
            float4 u0 = *(const float4*)&Usm[ty +  0][j4];
            float4 u1 = *(const float4*)&Usm[ty +  8][j4];
            float4 u2 = *(const float4*)&Usm[ty + 16][j4];
            float4 u3 = *(const float4*)&Usm[ty + 24][j4];
            #pragma unroll
            for (int l = 0; l < 4; l++) {
                float4 bv = *(const float4*)&sm.Bm[tx + 32 * l][j4];
                o[0][l] += u0.x * bv.x + u0.y * bv.y + u0.z * bv.z + u0.w * bv.w;
                o[1][l] += u1.x * bv.x + u1.y * bv.y + u1.z * bv.z + u1.w * bv.w;
                o[2][l] += u2.x * bv.x + u2.y * bv.y + u2.z * bv.z + u2.w * bv.w;
                o[3][l] += u3.x * bv.x + u3.y * bv.y + u3.z * bv.z + u3.w * bv.w;
            }
        }

        #pragma unroll
        for (int i = 0; i < 4; i++) {
            int n = ty + 8 * i;
            if (n0 + n < N_) {
                float* orow = &out[out_base + n * C3_ + c0 + tx];
                orow[0]  = o[i][0];
                orow[32] = o[i][1];
                orow[64] = o[i][2];
                orow[96] = o[i][3];
            }
        }
        __syncthreads();
    }
}

// ---------------------------------------------------------------------------
extern "C" void kernel_launch(void* const* d_in, const int* in_sizes, int n_in,
                              void* d_out, int out_size) {
    const float* tokens  = (const float*)d_in[0];
    const float* gate_w  = (const float*)d_in[1];
    const float* lora_a  = (const float*)d_in[2];
    const float* lora_b  = (const float*)d_in[3];
    const float* scaling = (const float*)d_in[4];
    float* out = (float*)d_out;

    int write_aux = (out_size >= OUT_TOTAL) ? 1 : 0;

    zero_pooled_kernel<<<B_, 1024>>>();
    pool_kernel<<<dim3(8, B_), 256>>>(tokens);
    router_kernel<<<4, 1024>>>(gate_w, out, write_aux);
    topk_kernel<<<1, 128>>>(scaling, out, write_aux);
    moe_lora_kernel<<<dim3((N_ + NT - 1) / NT, B_), 256>>>(tokens, lora_a, lora_b, out);
}

// round 4
// speedup vs baseline: 1.1055x; 1.1055x over previous
#include <cuda_runtime.h>
#include <math.h>

#define B_  16
#define N_  577
#define D_  1024
#define E_  8
#define R_  16
#define C3_ 3072
#define NPAD 640

#define WU_SIZE   (B_ * N_ * C3_)
#define RL_OFF    (WU_SIZE)
#define TI_OFF    (RL_OFF + B_ * E_)
#define EW_OFF    (TI_OFF + B_ * 2)
#define IMP_OFF   (EW_OFF + B_ * E_)
#define LOAD_OFF  (IMP_OFF + E_)

__device__ float g_part[8][B_][D_];
__device__ float g_pooled[B_][D_];
__device__ int   g_sel[B_][2];
__device__ float g_coef[B_][2];
__device__ float g_Ut[B_][32][NPAD];   // U transposed [b][j][n]

__device__ __forceinline__ void ffma2_acc(float2& d, float2 a, float2 b) {
    asm("fma.rn.f32x2 %0, %1, %2, %0;"
        : "+l"(reinterpret_cast<unsigned long long&>(d))
        : "l"(reinterpret_cast<unsigned long long&>(a)),
          "l"(reinterpret_cast<unsigned long long&>(b)));
}

// ---- Kernel 1: pooled partial sums (non-atomic) + zero g_Ut ----
__global__ __launch_bounds__(256) void prep_kernel(const float* __restrict__ tokens) {
    int bx = blockIdx.x;               // 0..127
    int b = bx >> 3, ch = bx & 7;
    int tid = threadIdx.x;
    int n0 = ch * 73, n1 = min(N_, n0 + 73);

    float4 acc = make_float4(0.f, 0.f, 0.f, 0.f);
    const float* base = tokens + (size_t)b * N_ * D_;
    for (int n = n0; n < n1; n++) {
        float4 v = *(const float4*)&base[n * D_ + tid * 4];
        acc.x += v.x; acc.y += v.y; acc.z += v.z; acc.w += v.w;
    }
    *(float4*)&g_part[ch][b][tid * 4] = acc;

    float4 z = make_float4(0.f, 0.f, 0.f, 0.f);
    for (int i = bx * 256 + tid; i < (B_ * 32 * NPAD) / 4; i += 128 * 256)
        ((float4*)g_Ut)[i] = z;
}

// ---- Kernel 2: reduce partials, router, top-2 softmax, aux outputs ----
__global__ void router_topk(const float* __restrict__ gate_w,
                            const float* __restrict__ scaling,
                            float* __restrict__ out) {
    __shared__ float logits_s[B_ * E_];
    __shared__ float ew[B_][E_];
    __shared__ int   sel_s[B_][2];
    int tid = threadIdx.x;

    for (int b = 0; b < B_; b++) {
        float s = 0.f;
        #pragma unroll
        for (int ch = 0; ch < 8; ch++) s += g_part[ch][b][tid];
        g_pooled[b][tid] = s;
    }
    __syncthreads();

    int w = tid >> 5, lane = tid & 31;
    for (int p = w; p < B_ * E_; p += 32) {
        int b = p >> 3, e = p & 7;
        float acc = 0.f;
        for (int d = lane; d < D_; d += 32)
            acc += g_pooled[b][d] * gate_w[d * E_ + e];
        #pragma unroll
        for (int o = 16; o; o >>= 1) acc += __shfl_down_sync(0xffffffffu, acc, o);
        if (lane == 0) {
            float lg = acc * (1.0f / (float)N_);
            logits_s[p] = lg;
            out[RL_OFF + p] = lg;
        }
    }
    __syncthreads();

    if (tid < B_ * E_) ew[tid >> 3][tid & 7] = 0.f;
    __syncthreads();

    if (tid < B_) {
        int b = tid;
        float v[E_];
        #pragma unroll
        for (int e = 0; e < E_; e++) v[e] = logits_s[b * E_ + e];
        int m1 = 0;
        #pragma unroll
        for (int e = 1; e < E_; e++) if (v[e] > v[m1]) m1 = e;
        int m2 = (m1 == 0) ? 1 : 0;
        #pragma unroll
        for (int e = 0; e < E_; e++) if (e != m1 && v[e] > v[m2]) m2 = e;

        float e2 = expf(v[m2] - v[m1]);
        float inv = 1.0f / (1.0f + e2);
        float w1 = inv, w2 = e2 * inv;

        ew[b][m1] = w1; ew[b][m2] = w2;
        sel_s[b][0] = m1; sel_s[b][1] = m2;
        g_sel[b][0] = m1; g_sel[b][1] = m2;
        g_coef[b][0] = w1 * scaling[m1];
        g_coef[b][1] = w2 * scaling[m2];
        out[TI_OFF + b * 2 + 0] = (float)m1;
        out[TI_OFF + b * 2 + 1] = (float)m2;
    }
    __syncthreads();

    if (tid < B_ * E_) out[EW_OFF + tid] = ew[tid >> 3][tid & 7];
    if (tid < E_) {
        float imp = 0.f; int ld = 0;
        for (int b = 0; b < B_; b++) {
            imp += ew[b][tid];
            ld += (sel_s[b][0] == tid) + (sel_s[b][1] == tid);
        }
        out[IMP_OFF + tid] = imp;
        out[LOAD_OFF + tid] = (float)ld;
    }
}

// ---- Kernel 3: U = (tokens @ Asel^T)*coef, transposed accumulate to g_Ut ----
#define UKC 64
__global__ __launch_bounds__(256) void u_kernel(const float* __restrict__ tokens,
                                                const float* __restrict__ lora_a) {
    __shared__ float Tsm[32][UKC + 4];
    __shared__ float Asm[32][UKC + 4];

    const int n0 = blockIdx.x * 32;
    const int b  = blockIdx.y;
    const int kq = blockIdx.z;          // k-half
    const int tid = threadIdx.x;

    const int s0 = g_sel[b][0], s1 = g_sel[b][1];
    const float c0f = g_coef[b][0], c1f = g_coef[b][1];

    const int kg   = tid >> 5;          // warp id = k-slice (warp-uniform)
    const int rowg = (tid >> 3) & 3;
    const int colg = tid & 7;

    float2 acc[8][4];
    #pragma unroll
    for (int i = 0; i < 8; i++)
        #pragma unroll
        for (int j = 0; j < 4; j++) acc[i][j] = make_float2(0.f, 0.f);

    const int kend = kq * 512 + 512;
    for (int k0 = kq * 512; k0 < kend; k0 += UKC) {
        #pragma unroll
        for (int t = 0; t < 2; t++) {
            int idx = tid + t * 256;
            int r = idx >> 4;
            int q = (idx & 15) * 4;
            float4 tv = make_float4(0.f, 0.f, 0.f, 0.f);
            if (n0 + r < N_)
                tv = *(const float4*)&tokens[((size_t)b * N_ + n0 + r) * D_ + k0 + q];
            *(float4*)&Tsm[r][q] = tv;

            int e = (r < 16) ? s0 : s1;
            float cf = (r < 16) ? c0f : c1f;
            float4 av = *(const float4*)&lora_a[((size_t)e * R_ + (r & 15)) * D_ + k0 + q];
            av.x *= cf; av.y *= cf; av.z *= cf; av.w *= cf;
            *(float4*)&Asm[r][q] = av;
        }
        __syncthreads();

        const int kb = kg * 8;
        #pragma unroll
        for (int ks = 0; ks < 8; ks += 4) {
            float4 avv[4];
            #pragma unroll
            for (int j = 0; j < 4; j++)
                avv[j] = *(const float4*)&Asm[colg + 8 * j][kb + ks];
            #pragma unroll
            for (int i = 0; i < 8; i++) {
                float4 tv = *(const float4*)&Tsm[rowg + 4 * i][kb + ks];
                #pragma unroll
                for (int j = 0; j < 4; j++) {
                    ffma2_acc(acc[i][j], make_float2(tv.x, tv.y),
                                         make_float2(avv[j].x, avv[j].y));
                    ffma2_acc(acc[i][j], make_float2(tv.z, tv.w),
                                         make_float2(avv[j].z, avv[j].w));
                }
            }
        }
        __syncthreads();
    }

    #pragma unroll
    for (int i = 0; i < 8; i++)
        #pragma unroll
        for (int j = 0; j < 4; j++)
            atomicAdd(&g_Ut[b][colg + 8 * j][n0 + rowg + 4 * i],
                      acc[i][j].x + acc[i][j].y);
}

// ---- Kernel 4: out[64n x 256c] = Ut^T @ Bsel^T ----
__global__ __launch_bounds__(256, 2) void out_kernel(const float* __restrict__ lora_b,
                                                     float* __restrict__ out) {
    __shared__ float Bsm[32][260];   // [k][c]
    __shared__ float Usm[32][68];    // [k][n]

    const int c0 = blockIdx.x * 256;
    const int n0 = blockIdx.y * 64;
    const int b  = blockIdx.z;
    const int tid = threadIdx.x;
    const int s0 = g_sel[b][0], s1 = g_sel[b][1];

    #pragma unroll
    for (int t = 0; t < 2; t++) {
        int idx = tid + t * 256;
        int k = idx >> 4;
        int nq = (idx & 15) * 4;
        *(float4*)&Usm[k][nq] = *(const float4*)&g_Ut[b][k][n0 + nq];
    }
    #pragma unroll
    for (int t = 0; t < 8; t++) {
        int idx = tid + t * 256;      // 0..2047
        int c  = idx & 255;
        int er = idx >> 8;            // 0..7
        int e  = (er >> 2) ? s1 : s0;
        int rq = er & 3;
        float4 v = *(const float4*)&lora_b[((size_t)e * C3_ + c0 + c) * R_ + rq * 4];
        int kb = (er >> 2) * 16 + rq * 4;
        Bsm[kb + 0][c] = v.x;
        Bsm[kb + 1][c] = v.y;
        Bsm[kb + 2][c] = v.z;
        Bsm[kb + 3][c] = v.w;
    }
    __syncthreads();

    const int rowg = tid >> 5;        // warp-uniform -> LDS broadcast
    const int cg4  = (tid & 31) * 4;

    float2 acc[8][4];
    #pragma unroll
    for (int i = 0; i < 8; i++)
        #pragma unroll
        for (int j = 0; j < 4; j++) acc[i][j] = make_float2(0.f, 0.f);

    #pragma unroll
    for (int k = 0; k < 32; k++) {
        float4 u0 = *(const float4*)&Usm[k][rowg * 4];
        float4 u1 = *(const float4*)&Usm[k][32 + rowg * 4];
        float4 b0 = *(const float4*)&Bsm[k][cg4];
        float4 b1 = *(const float4*)&Bsm[k][128 + cg4];
        float2 bp0 = make_float2(b0.x, b0.y);
        float2 bp1 = make_float2(b0.z, b0.w);
        float2 bp2 = make_float2(b1.x, b1.y);
        float2 bp3 = make_float2(b1.z, b1.w);
        float us[8] = {u0.x, u0.y, u0.z, u0.w, u1.x, u1.y, u1.z, u1.w};
        #pragma unroll
        for (int i = 0; i < 8; i++) {
            float2 ud = make_float2(us[i], us[i]);
            ffma2_acc(acc[i][0], ud, bp0);
            ffma2_acc(acc[i][1], ud, bp1);
            ffma2_acc(acc[i][2], ud, bp2);
            ffma2_acc(acc[i][3], ud, bp3);
        }
    }

    #pragma unroll
    for (int i = 0; i < 8; i++) {
        int n = n0 + ((i < 4) ? (rowg * 4 + i) : (32 + rowg * 4 + i - 4));
        if (n < N_) {
            float* orow = &out[((size_t)b * N_ + n) * C3_ + c0];
            float4 lo = make_float4(acc[i][0].x, acc[i][0].y, acc[i][1].x, acc[i][1].y);
            float4 hi = make_float4(acc[i][2].x, acc[i][2].y, acc[i][3].x, acc[i][3].y);
            *(float4*)&orow[cg4]       = lo;
            *(float4*)&orow[128 + cg4] = hi;
        }
    }
}

// ---------------------------------------------------------------------------
extern "C" void kernel_launch(void* const* d_in, const int* in_sizes, int n_in,
                              void* d_out, int out_size) {
    const float* tokens  = (const float*)d_in[0];
    const float* gate_w  = (const float*)d_in[1];
    const float* lora_a  = (const float*)d_in[2];
    const float* lora_b  = (const float*)d_in[3];
    const float* scaling = (const float*)d_in[4];
    float* out = (float*)d_out;

    prep_kernel<<<128, 256>>>(tokens);
    router_topk<<<1, 1024>>>(gate_w, scaling, out);
    u_kernel<<<dim3(19, B_, 2), 256>>>(tokens, lora_a);
    out_kernel<<<dim3(12, 10, B_), 256>>>(lora_b, out);
}

// round 5
// speedup vs baseline: 1.3801x; 1.2484x over previous
#include <cuda_runtime.h>
#include <math.h>

#define B_  16
#define N_  577
#define D_  1024
#define E_  8
#define R_  16
#define C3_ 3072
#define NPAD 640
#define NCH 16
#define KQ  4

#define WU_SIZE   (B_ * N_ * C3_)
#define RL_OFF    (WU_SIZE)
#define TI_OFF    (RL_OFF + B_ * E_)
#define EW_OFF    (TI_OFF + B_ * 2)
#define IMP_OFF   (EW_OFF + B_ * E_)
#define LOAD_OFF  (IMP_OFF + E_)

__device__ float g_part[NCH][B_][D_];
__device__ int   g_sel[B_][2];
__device__ float g_coef[B_][2];   // softmax weight * scaling
__device__ float g_w[B_][2];      // raw softmax weights (for importance/load)
__device__ float g_Ut[KQ][B_][32][NPAD];  // k-split partials of U^T

__device__ __forceinline__ void ffma2_acc(float2& d, float2 a, float2 b) {
    asm("fma.rn.f32x2 %0, %1, %2, %0;"
        : "+l"(reinterpret_cast<unsigned long long&>(d))
        : "l"(reinterpret_cast<unsigned long long&>(a)),
          "l"(reinterpret_cast<unsigned long long&>(b)));
}

// ---- Kernel 1: pooled partial sums over 16 n-chunks (non-atomic) ----
__global__ __launch_bounds__(256) void prep_kernel(const float* __restrict__ tokens) {
    int bx = blockIdx.x;               // 0..255
    int b = bx >> 4, ch = bx & 15;
    int tid = threadIdx.x;
    int n0 = ch * 37, n1 = min(N_, n0 + 37);

    float4 acc = make_float4(0.f, 0.f, 0.f, 0.f);
    const float* base = tokens + (size_t)b * N_ * D_;
    for (int n = n0; n < n1; n++) {
        float4 v = *(const float4*)&base[n * D_ + tid * 4];
        acc.x += v.x; acc.y += v.y; acc.z += v.z; acc.w += v.w;
    }
    *(float4*)&g_part[ch][b][tid * 4] = acc;
}

// ---- Kernel 2: per-batch logits + top-2 softmax + per-b aux outputs ----
__global__ __launch_bounds__(256) void logits_topk(const float* __restrict__ gate_w,
                                                   const float* __restrict__ scaling,
                                                   float* __restrict__ out) {
    __shared__ float pooled_s[D_];
    __shared__ float logits_s[E_];
    __shared__ int   m_s[2];
    __shared__ float w_s[2];

    const int b = blockIdx.x;
    const int tid = threadIdx.x;
    const int wid = tid >> 5, lane = tid & 31;

    // reduce 16 partials -> pooled sum (smem)
    float4 a = make_float4(0.f, 0.f, 0.f, 0.f);
    #pragma unroll
    for (int ch = 0; ch < NCH; ch++) {
        float4 v = *(const float4*)&g_part[ch][b][tid * 4];
        a.x += v.x; a.y += v.y; a.z += v.z; a.w += v.w;
    }
    *(float4*)&pooled_s[tid * 4] = a;
    __syncthreads();

    // warp wid computes logit for expert e = wid
    {
        float acc = 0.f;
        for (int d = lane; d < D_; d += 32)
            acc += pooled_s[d] * gate_w[d * E_ + wid];
        #pragma unroll
        for (int o = 16; o; o >>= 1) acc += __shfl_down_sync(0xffffffffu, acc, o);
        if (lane == 0) {
            float lg = acc * (1.0f / (float)N_);
            logits_s[wid] = lg;
            out[RL_OFF + b * E_ + wid] = lg;
        }
    }
    __syncthreads();

    if (tid == 0) {
        float v[E_];
        #pragma unroll
        for (int e = 0; e < E_; e++) v[e] = logits_s[e];
        int m1 = 0;
        #pragma unroll
        for (int e = 1; e < E_; e++) if (v[e] > v[m1]) m1 = e;
        int m2 = (m1 == 0) ? 1 : 0;
        #pragma unroll
        for (int e = 0; e < E_; e++) if (e != m1 && v[e] > v[m2]) m2 = e;

        float e2 = expf(v[m2] - v[m1]);
        float inv = 1.0f / (1.0f + e2);
        float w1 = inv, w2 = e2 * inv;

        m_s[0] = m1; m_s[1] = m2;
        w_s[0] = w1; w_s[1] = w2;
        g_sel[b][0] = m1; g_sel[b][1] = m2;
        g_w[b][0] = w1; g_w[b][1] = w2;
        g_coef[b][0] = w1 * scaling[m1];
        g_coef[b][1] = w2 * scaling[m2];
        out[TI_OFF + b * 2 + 0] = (float)m1;
        out[TI_OFF + b * 2 + 1] = (float)m2;
    }
    __syncthreads();

    if (tid < E_) {
        float w = (tid == m_s[0]) ? w_s[0] : ((tid == m_s[1]) ? w_s[1] : 0.f);
        out[EW_OFF + b * E_ + tid] = w;
    }
}

// ---- Kernel 3: U = (tokens @ Asel^T)*coef -> g_Ut[kq] (no atomics) ----
#define UKC 64
__global__ __launch_bounds__(256) void u_kernel(const float* __restrict__ tokens,
                                                const float* __restrict__ lora_a,
                                                float* __restrict__ out) {
    __shared__ union {
        struct { float T[32][UKC + 4]; float A[32][UKC + 4]; } p;
        float red[4][32][36];          // tree-reduction slices (conflict-free)
    } sm;

    const int n0 = blockIdx.x * 32;
    const int b  = blockIdx.y;
    const int kq = blockIdx.z;          // k-quarter: [kq*256, kq*256+256)
    const int tid = threadIdx.x;

    // importance / load aux (needs all b; runs after logits_topk)
    if (blockIdx.x == 0 && blockIdx.y == 0 && blockIdx.z == 0 && tid < E_) {
        float imp = 0.f; int ld = 0;
        for (int bb = 0; bb < B_; bb++) {
            if (g_sel[bb][0] == tid) { imp += g_w[bb][0]; ld++; }
            if (g_sel[bb][1] == tid) { imp += g_w[bb][1]; ld++; }
        }
        out[IMP_OFF + tid] = imp;
        out[LOAD_OFF + tid] = (float)ld;
    }

    const int s0 = g_sel[b][0], s1 = g_sel[b][1];
    const float c0f = g_coef[b][0], c1f = g_coef[b][1];

    const int kg   = tid >> 5;          // warp = k-slice within chunk
    const int rowg = (tid >> 3) & 3;
    const int colg = tid & 7;

    float2 acc[8][4];
    #pragma unroll
    for (int i = 0; i < 8; i++)
        #pragma unroll
        for (int j = 0; j < 4; j++) acc[i][j] = make_float2(0.f, 0.f);

    const int kend = kq * 256 + 256;
    for (int k0 = kq * 256; k0 < kend; k0 += UKC) {
        #pragma unroll
        for (int t = 0; t < 2; t++) {
            int idx = tid + t * 256;
            int r = idx >> 4;
            int q = (idx & 15) * 4;
            float4 tv = make_float4(0.f, 0.f, 0.f, 0.f);
            if (n0 + r < N_)
                tv = *(const float4*)&tokens[((size_t)b * N_ + n0 + r) * D_ + k0 + q];
            *(float4*)&sm.p.T[r][q] = tv;

            int e = (r < 16) ? s0 : s1;
            float cf = (r < 16) ? c0f : c1f;
            float4 av = *(const float4*)&lora_a[((size_t)e * R_ + (r & 15)) * D_ + k0 + q];
            av.x *= cf; av.y *= cf; av.z *= cf; av.w *= cf;
            *(float4*)&sm.p.A[r][q] = av;
        }
        __syncthreads();

        const int kb = kg * 8;
        #pragma unroll
        for (int ks = 0; ks < 8; ks += 4) {
            float4 avv[4];
            #pragma unroll
            for (int j = 0; j < 4; j++)
                avv[j] = *(const float4*)&sm.p.A[colg + 8 * j][kb + ks];
            #pragma unroll
            for (int i = 0; i < 8; i++) {
                float4 tv = *(const float4*)&sm.p.T[rowg + 4 * i][kb + ks];
                #pragma unroll
                for (int j = 0; j < 4; j++) {
                    ffma2_acc(acc[i][j], make_float2(tv.x, tv.y),
                                         make_float2(avv[j].x, avv[j].y));
                    ffma2_acc(acc[i][j], make_float2(tv.z, tv.w),
                                         make_float2(avv[j].z, avv[j].w));
                }
            }
        }
        __syncthreads();
    }

    // collapse pairs
    float v[8][4];
    #pragma unroll
    for (int i = 0; i < 8; i++)
        #pragma unroll
        for (int j = 0; j < 4; j++) v[i][j] = acc[i][j].x + acc[i][j].y;

    // cross-warp tree reduction (8 k-slices -> warp 0)
    for (int off = 4; off; off >>= 1) {
        if (kg >= off && kg < 2 * off) {
            #pragma unroll
            for (int i = 0; i < 8; i++)
                #pragma unroll
                for (int j = 0; j < 4; j++)
                    sm.red[kg - off][colg + 8 * j][rowg + 4 * i] = v[i][j];
        }
        __syncthreads();
        if (kg < off) {
            #pragma unroll
            for (int i = 0; i < 8; i++)
                #pragma unroll
                for (int j = 0; j < 4; j++)
                    v[i][j] += sm.red[kg][colg + 8 * j][rowg + 4 * i];
        }
        __syncthreads();
    }

    if (kg == 0) {
        #pragma unroll
        for (int i = 0; i < 8; i++)
            #pragma unroll
            for (int j = 0; j < 4; j++)
                g_Ut[kq][b][colg + 8 * j][n0 + rowg + 4 * i] = v[i][j];
    }
}

// ---- Kernel 4: out[64n x 256c] = sum_kq Ut[kq]^T @ Bsel^T ----
__global__ __launch_bounds__(256, 2) void out_kernel(const float* __restrict__ lora_b,
                                                     float* __restrict__ out) {
    __shared__ float Bsm[32][260];   // [k][c]
    __shared__ float Usm[32][68];    // [k][n]

    const int c0 = blockIdx.x * 256;
    const int n0 = blockIdx.y * 64;
    const int b  = blockIdx.z;
    const int tid = threadIdx.x;
    const int s0 = g_sel[b][0], s1 = g_sel[b][1];

    #pragma unroll
    for (int t = 0; t < 2; t++) {
        int idx = tid + t * 256;
        int k = idx >> 4;
        int nq = (idx & 15) * 4;
        float4 s = *(const float4*)&g_Ut[0][b][k][n0 + nq];
        #pragma unroll
        for (int q = 1; q < KQ; q++) {
            float4 p = *(const float4*)&g_Ut[q][b][k][n0 + nq];
            s.x += p.x; s.y += p.y; s.z += p.z; s.w += p.w;
        }
        *(float4*)&Usm[k][nq] = s;
    }
    #pragma unroll
    for (int t = 0; t < 8; t++) {
        int idx = tid + t * 256;      // 0..2047
        int c  = idx & 255;
        int er = idx >> 8;            // 0..7
        int e  = (er >> 2) ? s1 : s0;
        int rq = er & 3;
        float4 v = *(const float4*)&lora_b[((size_t)e * C3_ + c0 + c) * R_ + rq * 4];
        int kb = (er >> 2) * 16 + rq * 4;
        Bsm[kb + 0][c] = v.x;
        Bsm[kb + 1][c] = v.y;
        Bsm[kb + 2][c] = v.z;
        Bsm[kb + 3][c] = v.w;
    }
    __syncthreads();

    const int rowg = tid >> 5;        // warp-uniform
    const int cg4  = (tid & 31) * 4;

    float2 acc[8][4];
    #pragma unroll
    for (int i = 0; i < 8; i++)
        #pragma unroll
        for (int j = 0; j < 4; j++) acc[i][j] = make_float2(0.f, 0.f);

    #pragma unroll
    for (int k = 0; k < 32; k++) {
        float4 u0 = *(const float4*)&Usm[k][rowg * 4];
        float4 u1 = *(const float4*)&Usm[k][32 + rowg * 4];
        float4 b0 = *(const float4*)&Bsm[k][cg4];
        float4 b1 = *(const float4*)&Bsm[k][128 + cg4];
        float2 bp0 = make_float2(b0.x, b0.y);
        float2 bp1 = make_float2(b0.z, b0.w);
        float2 bp2 = make_float2(b1.x, b1.y);
        float2 bp3 = make_float2(b1.z, b1.w);
        float us[8] = {u0.x, u0.y, u0.z, u0.w, u1.x, u1.y, u1.z, u1.w};
        #pragma unroll
        for (int i = 0; i < 8; i++) {
            float2 ud = make_float2(us[i], us[i]);
            ffma2_acc(acc[i][0], ud, bp0);
            ffma2_acc(acc[i][1], ud, bp1);
            ffma2_acc(acc[i][2], ud, bp2);
            ffma2_acc(acc[i][3], ud, bp3);
        }
    }

    #pragma unroll
    for (int i = 0; i < 8; i++) {
        int n = n0 + ((i < 4) ? (rowg * 4 + i) : (32 + rowg * 4 + i - 4));
        if (n < N_) {
            float* orow = &out[((size_t)b * N_ + n) * C3_ + c0];
            *(float4*)&orow[cg4] =
                make_float4(acc[i][0].x, acc[i][0].y, acc[i][1].x, acc[i][1].y);
            *(float4*)&orow[128 + cg4] =
                make_float4(acc[i][2].x, acc[i][2].y, acc[i][3].x, acc[i][3].y);
        }
    }
}

// ---------------------------------------------------------------------------
extern "C" void kernel_launch(void* const* d_in, const int* in_sizes, int n_in,
                              void* d_out, int out_size) {
    const float* tokens  = (const float*)d_in[0];
    const float* gate_w  = (const float*)d_in[1];
    const float* lora_a  = (const float*)d_in[2];
    const float* lora_b  = (const float*)d_in[3];
    const float* scaling = (const float*)d_in[4];
    float* out = (float*)d_out;

    prep_kernel<<<256, 256>>>(tokens);
    logits_topk<<<B_, 256>>>(gate_w, scaling, out);
    u_kernel<<<dim3(19, B_, KQ), 256>>>(tokens, lora_a, out);
    out_kernel<<<dim3(12, 10, B_), 256>>>(lora_b, out);
}

// round 8
// speedup vs baseline: 1.4016x; 1.0156x over previous
#include <cuda_runtime.h>
#include <math.h>

#define B_  16
#define N_  577
#define D_  1024
#define E_  8
#define R_  16
#define C3_ 3072
#define NPAD 640
#define NCH 16
#define KQ  2

#define WU_SIZE   (B_ * N_ * C3_)
#define RL_OFF    (WU_SIZE)
#define TI_OFF    (RL_OFF + B_ * E_)
#define EW_OFF    (TI_OFF + B_ * 2)
#define IMP_OFF   (EW_OFF + B_ * E_)
#define LOAD_OFF  (IMP_OFF + E_)

__device__ float g_part[NCH][B_][D_];
__device__ int   g_sel[B_][2];
__device__ float g_coef[B_][2];
__device__ float g_w[B_][2];
__device__ float g_Ut[KQ][B_][32][NPAD];  // k-split partials of U^T

__device__ __forceinline__ void ffma2_acc(float2& d, float2 a, float2 b) {
    asm("fma.rn.f32x2 %0, %1, %2, %0;"
        : "+l"(reinterpret_cast<unsigned long long&>(d))
        : "l"(reinterpret_cast<unsigned long long&>(a)),
          "l"(reinterpret_cast<unsigned long long&>(b)));
}

// ---- Kernel 1: pooled partial sums over 16 n-chunks ----
__global__ __launch_bounds__(256) void prep_kernel(const float* __restrict__ tokens) {
    int bx = blockIdx.x;
    int b = bx >> 4, ch = bx & 15;
    int tid = threadIdx.x;
    int n0 = ch * 37, n1 = min(N_, n0 + 37);

    float4 acc = make_float4(0.f, 0.f, 0.f, 0.f);
    const float* base = tokens + (size_t)b * N_ * D_;
    for (int n = n0; n < n1; n++) {
        float4 v = *(const float4*)&base[n * D_ + tid * 4];
        acc.x += v.x; acc.y += v.y; acc.z += v.z; acc.w += v.w;
    }
    *(float4*)&g_part[ch][b][tid * 4] = acc;
}

// ---- Kernel 2: per-batch logits + top-2 softmax + aux outputs ----
__global__ __launch_bounds__(256) void logits_topk(const float* __restrict__ gate_w,
                                                   const float* __restrict__ scaling,
                                                   float* __restrict__ out) {
    __shared__ float pooled_s[D_];
    __shared__ float logits_s[E_];
    __shared__ int   m_s[2];
    __shared__ float w_s[2];

    const int b = blockIdx.x;
    const int tid = threadIdx.x;
    const int wid = tid >> 5, lane = tid & 31;

    float4 a = make_float4(0.f, 0.f, 0.f, 0.f);
    #pragma unroll
    for (int ch = 0; ch < NCH; ch++) {
        float4 v = *(const float4*)&g_part[ch][b][tid * 4];
        a.x += v.x; a.y += v.y; a.z += v.z; a.w += v.w;
    }
    *(float4*)&pooled_s[tid * 4] = a;
    __syncthreads();

    {
        float acc = 0.f;
        for (int d = lane; d < D_; d += 32)
            acc += pooled_s[d] * gate_w[d * E_ + wid];
        #pragma unroll
        for (int o = 16; o; o >>= 1) acc += __shfl_down_sync(0xffffffffu, acc, o);
        if (lane == 0) {
            float lg = acc * (1.0f / (float)N_);
            logits_s[wid] = lg;
            out[RL_OFF + b * E_ + wid] = lg;
        }
    }
    __syncthreads();

    if (tid == 0) {
        float v[E_];
        #pragma unroll
        for (int e = 0; e < E_; e++) v[e] = logits_s[e];
        int m1 = 0;
        #pragma unroll
        for (int e = 1; e < E_; e++) if (v[e] > v[m1]) m1 = e;
        int m2 = (m1 == 0) ? 1 : 0;
        #pragma unroll
        for (int e = 0; e < E_; e++) if (e != m1 && v[e] > v[m2]) m2 = e;

        float e2 = expf(v[m2] - v[m1]);
        float inv = 1.0f / (1.0f + e2);
        float w1 = inv, w2 = e2 * inv;

        m_s[0] = m1; m_s[1] = m2;
        w_s[0] = w1; w_s[1] = w2;
        g_sel[b][0] = m1; g_sel[b][1] = m2;
        g_w[b][0] = w1; g_w[b][1] = w2;
        g_coef[b][0] = w1 * scaling[m1];
        g_coef[b][1] = w2 * scaling[m2];
        out[TI_OFF + b * 2 + 0] = (float)m1;
        out[TI_OFF + b * 2 + 1] = (float)m2;
    }
    __syncthreads();

    if (tid < E_) {
        float w = (tid == m_s[0]) ? w_s[0] : ((tid == m_s[1]) ? w_s[1] : 0.f);
        out[EW_OFF + b * E_ + tid] = w;
    }
}

// ---- Kernel 3: U partials, smem-transposed COALESCED stores ----
#define UKC 64
__global__ __launch_bounds__(256) void u_kernel(const float* __restrict__ tokens,
                                                const float* __restrict__ lora_a,
                                                float* __restrict__ out) {
    __shared__ union {
        struct { float T[32][UKC + 4]; float A[32][UKC + 4]; } p;
        float red[4][32][36];
    } sm;

    const int n0 = blockIdx.x * 32;
    const int b  = blockIdx.y;
    const int kq = blockIdx.z;          // k-half: [kq*512, +512)
    const int tid = threadIdx.x;

    if (blockIdx.x == 0 && blockIdx.y == 0 && blockIdx.z == 0 && tid < E_) {
        float imp = 0.f; int ld = 0;
        for (int bb = 0; bb < B_; bb++) {
            if (g_sel[bb][0] == tid) { imp += g_w[bb][0]; ld++; }
            if (g_sel[bb][1] == tid) { imp += g_w[bb][1]; ld++; }
        }
        out[IMP_OFF + tid] = imp;
        out[LOAD_OFF + tid] = (float)ld;
    }

    const int s0 = g_sel[b][0], s1 = g_sel[b][1];
    const float c0f = g_coef[b][0], c1f = g_coef[b][1];

    const int kg   = tid >> 5;
    const int rowg = (tid >> 3) & 3;
    const int colg = tid & 7;

    float2 acc[8][4];
    #pragma unroll
    for (int i = 0; i < 8; i++)
        #pragma unroll
        for (int j = 0; j < 4; j++) acc[i][j] = make_float2(0.f, 0.f);

    const int kend = kq * 512 + 512;
    for (int k0 = kq * 512; k0 < kend; k0 += UKC) {
        #pragma unroll
        for (int t = 0; t < 2; t++) {
            int idx = tid + t * 256;
            int r = idx >> 4;
            int q = (idx & 15) * 4;
            float4 tv = make_float4(0.f, 0.f, 0.f, 0.f);
            if (n0 + r < N_)
                tv = *(const float4*)&tokens[((size_t)b * N_ + n0 + r) * D_ + k0 + q];
            *(float4*)&sm.p.T[r][q] = tv;

            int e = (r < 16) ? s0 : s1;
            float cf = (r < 16) ? c0f : c1f;
            float4 av = *(const float4*)&lora_a[((size_t)e * R_ + (r & 15)) * D_ + k0 + q];
            av.x *= cf; av.y *= cf; av.z *= cf; av.w *= cf;
            *(float4*)&sm.p.A[r][q] = av;
        }
        __syncthreads();

        const int kb = kg * 8;
        #pragma unroll
        for (int ks = 0; ks < 8; ks += 4) {
            float4 avv[4];
            #pragma unroll
            for (int j = 0; j < 4; j++)
                avv[j] = *(const float4*)&sm.p.A[colg + 8 * j][kb + ks];
            #pragma unroll
            for (int i = 0; i < 8; i++) {
                float4 tv = *(const float4*)&sm.p.T[rowg + 4 * i][kb + ks];
                #pragma unroll
                for (int j = 0; j < 4; j++) {
                    ffma2_acc(acc[i][j], make_float2(tv.x, tv.y),
                                         make_float2(avv[j].x, avv[j].y));
                    ffma2_acc(acc[i][j], make_float2(tv.z, tv.w),
                                         make_float2(avv[j].z, avv[j].w));
                }
            }
        }
        __syncthreads();
    }

    float v[8][4];
    #pragma unroll
    for (int i = 0; i < 8; i++)
        #pragma unroll
        for (int j = 0; j < 4; j++) v[i][j] = acc[i][j].x + acc[i][j].y;

    // cross-warp tree reduction into warp 0
    for (int off = 4; off; off >>= 1) {
        if (kg >= off && kg < 2 * off) {
            #pragma unroll
            for (int i = 0; i < 8; i++)
                #pragma unroll
                for (int j = 0; j < 4; j++)
                    sm.red[kg - off][colg + 8 * j][rowg + 4 * i] = v[i][j];
        }
        __syncthreads();
        if (kg < off) {
            #pragma unroll
            for (int i = 0; i < 8; i++)
                #pragma unroll
                for (int j = 0; j < 4; j++)
                    v[i][j] += sm.red[kg][colg + 8 * j][rowg + 4 * i];
        }
        __syncthreads();
    }

    // warp 0 drops the tile into smem; ALL threads store coalesced float4 rows
    if (kg == 0) {
        #pragma unroll
        for (int i = 0; i < 8; i++)
            #pragma unroll
            for (int j = 0; j < 4; j++)
                sm.red[0][colg + 8 * j][rowg + 4 * i] = v[i][j];
    }
    __syncthreads();
    {
        int j  = tid >> 3;
        int nq = (tid & 7) * 4;
        *(float4*)&g_Ut[kq][b][j][n0 + nq] = *(const float4*)&sm.red[0][j][nq];
    }
}

// ---- Kernel 4: out[64n x 256c] = (Ut0+Ut1)^T @ Bsel^T ----
__global__ __launch_bounds__(256, 3) void out_kernel(const float* __restrict__ lora_b,
                                                     float* __restrict__ out) {
    __shared__ float Bsm[32][260];
    __shared__ float Usm[32][68];

    const int c0 = blockIdx.x * 256;
    const int n0 = blockIdx.y * 64;
    const int b  = blockIdx.z;
    const int tid = threadIdx.x;
    const int s0 = g_sel[b][0], s1 = g_sel[b][1];

    #pragma unroll
    for (int t = 0; t < 2; t++) {
        int idx = tid + t * 256;
        int k = idx >> 4;
        int nq = (idx & 15) * 4;
        float4 s = *(const float4*)&g_Ut[0][b][k][n0 + nq];
        float4 p = *(const float4*)&g_Ut[1][b][k][n0 + nq];
        s.x += p.x; s.y += p.y; s.z += p.z; s.w += p.w;
        *(float4*)&Usm[k][nq] = s;
    }
    #pragma unroll
    for (int t = 0; t < 8; t++) {
        int idx = tid + t * 256;
        int c  = idx & 255;
        int er = idx >> 8;
        int e  = (er >> 2) ? s1 : s0;
        int rq = er & 3;
        float4 v = *(const float4*)&lora_b[((size_t)e * C3_ + c0 + c) * R_ + rq * 4];
        int kb = (er >> 2) * 16 + rq * 4;
        Bsm[kb + 0][c] = v.x;
        Bsm[kb + 1][c] = v.y;
        Bsm[kb + 2][c] = v.z;
        Bsm[kb + 3][c] = v.w;
    }
    __syncthreads();

    const int rowg = tid >> 5;
    const int cg4  = (tid & 31) * 4;

    float2 acc[8][4];
    #pragma unroll
    for (int i = 0; i < 8; i++)
        #pragma unroll
        for (int j = 0; j < 4; j++) acc[i][j] = make_float2(0.f, 0.f);

    #pragma unroll
    for (int k = 0; k < 32; k++) {
        float4 u0 = *(const float4*)&Usm[k][rowg * 4];
        float4 u1 = *(const float4*)&Usm[k][32 + rowg * 4];
        float4 b0 = *(const float4*)&Bsm[k][cg4];
        float4 b1 = *(const float4*)&Bsm[k][128 + cg4];
        float2 bp0 = make_float2(b0.x, b0.y);
        float2 bp1 = make_float2(b0.z, b0.w);
        float2 bp2 = make_float2(b1.x, b1.y);
        float2 bp3 = make_float2(b1.z, b1.w);
        float us[8] = {u0.x, u0.y, u0.z, u0.w, u1.x, u1.y, u1.z, u1.w};
        #pragma unroll
        for (int i = 0; i < 8; i++) {
            float2 ud = make_float2(us[i], us[i]);
            ffma2_acc(acc[i][0], ud, bp0);
            ffma2_acc(acc[i][1], ud, bp1);
            ffma2_acc(acc[i][2], ud, bp2);
            ffma2_acc(acc[i][3], ud, bp3);
        }
    }

    #pragma unroll
    for (int i = 0; i < 8; i++) {
        int n = n0 + ((i < 4) ? (rowg * 4 + i) : (32 + rowg * 4 + i - 4));
        if (n < N_) {
            float* orow = &out[((size_t)b * N_ + n) * C3_ + c0];
            *(float4*)&orow[cg4] =
                make_float4(acc[i][0].x, acc[i][0].y, acc[i][1].x, acc[i][1].y);
            *(float4*)&orow[128 + cg4] =
                make_float4(acc[i][2].x, acc[i][2].y, acc[i][3].x, acc[i][3].y);
        }
    }
}

// ---------------------------------------------------------------------------
extern "C" void kernel_launch(void* const* d_in, const int* in_sizes, int n_in,
                              void* d_out, int out_size) {
    const float* tokens  = (const float*)d_in[0];
    const float* gate_w  = (const float*)d_in[1];
    const float* lora_a  = (const float*)d_in[2];
    const float* lora_b  = (const float*)d_in[3];
    const float* scaling = (const float*)d_in[4];
    float* out = (float*)d_out;

    prep_kernel<<<256, 256>>>(tokens);
    logits_topk<<<B_, 256>>>(gate_w, scaling, out);
    u_kernel<<<dim3(19, B_, KQ), 256>>>(tokens, lora_a, out);
    out_kernel<<<dim3(12, 10, B_), 256>>>(lora_b, out);
}